// round 16
// baseline (speedup 1.0000x reference)
#include <cuda_runtime.h>
#include <cuda_bf16.h>
#include <cstdint>

typedef unsigned long long ull;
typedef unsigned int uint32;

#define TT   128
#define BB   64
#define HS   72          /* padded global h row stride (floats) */
#define HH   512
#define EE   256
#define VV   5000
#define NSTEP 255
#define NCOLS_E 8192
#define NCOLS_D 8128
#define RNN_CTAS 128
#define RNN_THREADS 512
/* rnn smem (floats): wf0 8192 | wf1 16384 | stage 2x(128x72)=18432 | P0 4352 | P1 4352 | mbar 4 */
#define WF0_F  0
#define WF1_F  8192
#define STG_F  24576
#define STG_BUF_F 9216
#define P0_F   43008
#define P1_F   47360
#define MB_F   51712
#define RNN_SMEM_FLOATS 51716
#define RNN_SMEM_BYTES  (RNN_SMEM_FLOATS * 4)
#define CHUNK_BYTES (128 * HS * 4)   /* 36864 */

/* ---------------- device scratch (static, no allocation) ---------------- */
__device__ float g_xe[NCOLS_E][EE];
__device__ float g_xd[NCOLS_D][EE];
__device__ float g_pre_e[TT][HH][BB][4];
__device__ float g_pre_d[TT - 1][HH][BB][4];
__device__ float g_wf0e[RNN_CTAS][8192];
__device__ float g_wf0d[RNN_CTAS][8192];
__device__ float g_wf1e[RNN_CTAS][16384];
__device__ float g_wf1d[RNN_CTAS][16384];
__device__ float g_h0[2][HH][HS];
__device__ float g_h1[2][HH][HS];
__device__ float g_hist[NCOLS_D][HH];
__device__ unsigned g_count;

/* ---------------- helpers ---------------- */
__device__ __forceinline__ void fma2(ull& acc, ull a, ull b) {
    asm("fma.rn.f32x2 %0, %1, %2, %0;" : "+l"(acc) : "l"(a), "l"(b));
}
__device__ __forceinline__ ull splat2(float x) {
    ull r; unsigned u = __float_as_uint(x);
    asm("mov.b64 %0, {%1, %1};" : "=l"(r) : "r"(u));
    return r;
}
__device__ __forceinline__ float2 unpack2(ull v) {
    unsigned lo, hi;
    asm("mov.b64 {%0, %1}, %2;" : "=r"(lo), "=r"(hi) : "l"(v));
    float2 f; f.x = __uint_as_float(lo); f.y = __uint_as_float(hi);
    return f;
}
__device__ __forceinline__ float sigf(float x) { return 1.0f / (1.0f + __expf(-x)); }
__device__ __forceinline__ uint32 tf32r(float x) {
    uint32 r; asm("cvt.rna.tf32.f32 %0, %1;" : "=r"(r) : "f"(x));
    return r;
}
__device__ __forceinline__ void mma_tf32(float* c,
                                         uint32 a0, uint32 a1, uint32 a2, uint32 a3,
                                         uint32 b0, uint32 b1) {
    asm volatile(
        "mma.sync.aligned.m16n8k8.row.col.f32.tf32.tf32.f32 "
        "{%0,%1,%2,%3}, {%4,%5,%6,%7}, {%8,%9}, {%0,%1,%2,%3};"
        : "+f"(c[0]), "+f"(c[1]), "+f"(c[2]), "+f"(c[3])
        : "r"(a0), "r"(a1), "r"(a2), "r"(a3), "r"(b0), "r"(b1));
}
__device__ __forceinline__ void mbar_init(uint32 mbar, uint32 cnt) {
    asm volatile("mbarrier.init.shared.b64 [%0], %1;" :: "r"(mbar), "r"(cnt) : "memory");
}
__device__ __forceinline__ void mbar_expect_tx(uint32 mbar, uint32 bytes) {
    asm volatile("mbarrier.arrive.expect_tx.shared.b64 _, [%0], %1;"
                 :: "r"(mbar), "r"(bytes) : "memory");
}
__device__ __forceinline__ void bulk_copy(uint32 sdst, const void* gsrc, uint32 bytes,
                                          uint32 mbar) {
    asm volatile("cp.async.bulk.shared::cta.global.mbarrier::complete_tx::bytes "
                 "[%0], [%1], %2, [%3];"
                 :: "r"(sdst), "l"(gsrc), "r"(bytes), "r"(mbar) : "memory");
}
__device__ __forceinline__ void mbar_wait(uint32 mbar, uint32 parity) {
    uint32 done;
    asm volatile("{\n\t.reg .pred p;\n\t"
                 "mbarrier.try_wait.parity.acquire.cta.shared::cta.b64 p, [%1], %2;\n\t"
                 "selp.b32 %0, 1, 0, p;\n\t}"
                 : "=r"(done) : "r"(mbar), "r"(parity) : "memory");
    if (!done) {
        asm volatile("{\n\t.reg .pred P1;\n\t"
                     "WL_%=:\n\t"
                     "mbarrier.try_wait.parity.acquire.cta.shared::cta.b64 P1, [%0], %1, 0x989680;\n\t"
                     "@P1 bra.uni WD_%=;\n\t"
                     "bra.uni WL_%=;\n\t"
                     "WD_%=:\n\t}"
                     :: "r"(mbar), "r"(parity) : "memory");
    }
}

/* ---------------- setup ---------------- */
__global__ void setup_kernel(float* __restrict__ out,
                             const float* __restrict__ embE, const int* __restrict__ src,
                             const float* __restrict__ embD, const int* __restrict__ trg) {
    int i = blockIdx.x * blockDim.x + threadIdx.x;
    if (i < NCOLS_E * 64) {
        int col = i >> 6, e4 = i & 63;
        ((float4*)&g_xe[0][0])[(size_t)col * 64 + e4] =
            ((const float4*)embE)[(size_t)src[col] * 64 + e4];
    } else if (i < NCOLS_E * 64 + NCOLS_D * 64) {
        int j2 = i - NCOLS_E * 64;
        int col = j2 >> 6, e4 = j2 & 63;
        ((float4*)&g_xd[0][0])[(size_t)col * 64 + e4] =
            ((const float4*)embD)[(size_t)trg[col] * 64 + e4];
    }
    if (i < BB * VV) out[i] = 0.0f;
    if (i < 2 * HH * HS) {
        (&g_h0[0][0][0])[i] = 0.0f;
        (&g_h1[0][0][0])[i] = 0.0f;
    }
    if (i == 0) g_count = 0u;
}

/* ---------------- weight repack into mma fragment order (tf32-rounded) ---------------- */
__global__ void repack_kernel(const float* __restrict__ eWhh0, const float* __restrict__ dWhh0,
                              const float* __restrict__ eWih1, const float* __restrict__ eWhh1,
                              const float* __restrict__ dWih1, const float* __restrict__ dWhh1) {
    int stride = gridDim.x * blockDim.x;
    int idx = blockIdx.x * blockDim.x + threadIdx.x;
    for (int i = idx; i < RNN_CTAS * 8192; i += stride) {
        int j = i & 3, l = (i >> 2) & 31, c = (i >> 7) & 63, cta = i >> 13;
        int m = (l >> 2) + ((j & 1) << 3);
        int k = 8 * c + (l & 3) + ((j >> 1) << 2);
        int u = cta * 4 + (m >> 2), g = m & 3;
        size_t off = (size_t)(g * HH + u) * HH + k;
        g_wf0e[cta][i & 8191] = __uint_as_float(tf32r(eWhh0[off]));
        g_wf0d[cta][i & 8191] = __uint_as_float(tf32r(dWhh0[off]));
    }
    for (int i = idx; i < RNN_CTAS * 16384; i += stride) {
        int j = i & 3, l = (i >> 2) & 31, c = (i >> 7) & 127, cta = i >> 14;
        int m = (l >> 2) + ((j & 1) << 3);
        int k = 8 * c + (l & 3) + ((j >> 1) << 2);
        int u = cta * 4 + (m >> 2), g = m & 3;
        float ve, vd;
        if (k < HH) { ve = eWih1[(size_t)(g * HH + u) * HH + k];
                      vd = dWih1[(size_t)(g * HH + u) * HH + k]; }
        else        { ve = eWhh1[(size_t)(g * HH + u) * HH + (k - HH)];
                      vd = dWhh1[(size_t)(g * HH + u) * HH + (k - HH)]; }
        g_wf1e[cta][i & 16383] = __uint_as_float(tf32r(ve));
        g_wf1d[cta][i & 16383] = __uint_as_float(tf32r(vd));
    }
}

/* ---------------- fp32 64x64 GEMM for layer-0 preactivations (mode-0 only) ---------------- */
__global__ void __launch_bounds__(256) gemm_kernel(
    const float* __restrict__ Aenc, const float* __restrict__ Adec,
    int M, int K,
    const float* __restrict__ biasE, const float* __restrict__ biasD) {
    __shared__ float As[32][64];
    __shared__ float Bs[32][64];

    int tid = threadIdx.x;
    int r = (tid & 15) << 2;
    int c = (tid >> 4) << 2;
    int m0 = blockIdx.y * 64;

    bool dec = (blockIdx.x >= NCOLS_E / 64);
    const float* A    = dec ? Adec : Aenc;
    const float* bias = dec ? biasD : biasE;
    const float* B    = dec ? &g_xd[0][0] : &g_xe[0][0];
    float* dst        = dec ? &g_pre_d[0][0][0][0] : &g_pre_e[0][0][0][0];
    int n0 = (dec ? (int)blockIdx.x - NCOLS_E / 64 : (int)blockIdx.x) * 64;

    ull acc[4][2];
    #pragma unroll
    for (int i = 0; i < 4; i++) { acc[i][0] = 0ull; acc[i][1] = 0ull; }

    for (int kt = 0; kt < K; kt += 32) {
        #pragma unroll
        for (int rep = 0; rep < 2; rep++) {
            int f = tid + rep * 256;
            int m = f >> 3;
            int k4 = (f & 7) << 2;
            float4 va = *(const float4*)&A[(size_t)(m0 + m) * K + kt + k4];
            As[k4 + 0][m] = va.x; As[k4 + 1][m] = va.y;
            As[k4 + 2][m] = va.z; As[k4 + 3][m] = va.w;
            float4 vb = *(const float4*)&B[(size_t)(n0 + m) * K + kt + k4];
            Bs[k4 + 0][m] = vb.x; Bs[k4 + 1][m] = vb.y;
            Bs[k4 + 2][m] = vb.z; Bs[k4 + 3][m] = vb.w;
        }
        __syncthreads();
        #pragma unroll
        for (int k = 0; k < 32; k++) {
            float4 av = *(const float4*)&As[k][r];
            float4 bv = *(const float4*)&Bs[k][c];
            ull b01 = ((const ull*)&bv)[0];
            ull b23 = ((const ull*)&bv)[1];
            ull a0 = splat2(av.x), a1 = splat2(av.y), a2 = splat2(av.z), a3 = splat2(av.w);
            fma2(acc[0][0], a0, b01); fma2(acc[0][1], a0, b23);
            fma2(acc[1][0], a1, b01); fma2(acc[1][1], a1, b23);
            fma2(acc[2][0], a2, b01); fma2(acc[2][1], a2, b23);
            fma2(acc[3][0], a3, b01); fma2(acc[3][1], a3, b23);
        }
        __syncthreads();
    }

    #pragma unroll
    for (int i = 0; i < 4; i++) {
        int m = m0 + r + i;
        float bval = bias[m];
        float2 v01 = unpack2(acc[i][0]);
        float2 v23 = unpack2(acc[i][1]);
        float vals[4] = { v01.x + bval, v01.y + bval, v23.x + bval, v23.y + bval };
        #pragma unroll
        for (int j = 0; j < 4; j++) {
            int n = n0 + c + j;
            int t = n >> 6, b = n & 63;
            int uu = m & 511, g = m >> 9;
            dst[(((size_t)t * HH + uu) * BB + b) * 4 + g] = vals[j];
        }
    }
}

/* ---------------- tf32-mma fc GEMM + similarity-mask epilogue ----------------
   out[(n+64)*VV + m] = (fcW[m]·hist[n] + fcb[m]) * mult(m, src[n], src[n+64])
   Tile 64m x 64n, K staged 32/iter. 8 warps = 2(m) x 4(n); each warp 32m x 16n.
   As[64][36] (A-frag LDS conflict-free), Bs[32][68] ([k][n], 2-way on frag).     */
__global__ void __launch_bounds__(256) fc_tc_kernel(
    const float* __restrict__ A,     /* fcW [VV][HH] */
    const float* __restrict__ bias,
    const int* __restrict__ src, const float* __restrict__ vs,
    float* __restrict__ outp) {
    __shared__ float As[64 * 36];
    __shared__ float Bs[32 * 68];
    const float* B = &g_hist[0][0];

    int tid = threadIdx.x;
    int lane = tid & 31, warp = tid >> 5;
    int mw = warp >> 2, nw = warp & 3;
    int m0 = blockIdx.y * 64, n0 = blockIdx.x * 64;
    int lq = lane >> 2, lr = lane & 3;

    float c[2][2][4];
    #pragma unroll
    for (int mt = 0; mt < 2; mt++)
        #pragma unroll
        for (int nt = 0; nt < 2; nt++)
            #pragma unroll
            for (int q = 0; q < 4; q++) c[mt][nt][q] = 0.f;

    for (int kt = 0; kt < HH; kt += 32) {
        #pragma unroll
        for (int rep = 0; rep < 2; rep++) {
            int idx = tid + rep * 256;
            int row = idx >> 3, k4 = (idx & 7) << 2;
            int gm = m0 + row;
            float4 va = make_float4(0.f, 0.f, 0.f, 0.f);
            if (gm < VV) va = *(const float4*)&A[(size_t)gm * HH + kt + k4];
            As[row * 36 + k4 + 0] = __uint_as_float(tf32r(va.x));
            As[row * 36 + k4 + 1] = __uint_as_float(tf32r(va.y));
            As[row * 36 + k4 + 2] = __uint_as_float(tf32r(va.z));
            As[row * 36 + k4 + 3] = __uint_as_float(tf32r(va.w));
            float4 vb = *(const float4*)&B[(size_t)(n0 + row) * HH + kt + k4];
            Bs[(k4 + 0) * 68 + row] = __uint_as_float(tf32r(vb.x));
            Bs[(k4 + 1) * 68 + row] = __uint_as_float(tf32r(vb.y));
            Bs[(k4 + 2) * 68 + row] = __uint_as_float(tf32r(vb.z));
            Bs[(k4 + 3) * 68 + row] = __uint_as_float(tf32r(vb.w));
        }
        __syncthreads();
        #pragma unroll
        for (int ks = 0; ks < 4; ks++) {
            float bf[2][2];
            #pragma unroll
            for (int nt = 0; nt < 2; nt++)
                #pragma unroll
                for (int j = 0; j < 2; j++)
                    bf[nt][j] = Bs[(ks * 8 + lr + 4 * j) * 68 + nw * 16 + nt * 8 + lq];
            #pragma unroll
            for (int mt = 0; mt < 2; mt++) {
                int rbase = mw * 32 + mt * 16 + lq;
                float af[4];
                #pragma unroll
                for (int j = 0; j < 4; j++)
                    af[j] = As[(rbase + 8 * (j & 1)) * 36 + ks * 8 + lr + 4 * (j >> 1)];
                #pragma unroll
                for (int nt = 0; nt < 2; nt++)
                    mma_tf32(c[mt][nt],
                             __float_as_uint(af[0]), __float_as_uint(af[1]),
                             __float_as_uint(af[2]), __float_as_uint(af[3]),
                             __float_as_uint(bf[nt][0]), __float_as_uint(bf[nt][1]));
            }
        }
        __syncthreads();
    }

    /* epilogue: C frag row = +8*(q>>1), col lsb = q&1 */
    #pragma unroll
    for (int mt = 0; mt < 2; mt++) {
        #pragma unroll
        for (int nt = 0; nt < 2; nt++) {
            #pragma unroll
            for (int q = 0; q < 4; q++) {
                int m = m0 + mw * 32 + mt * 16 + lq + 8 * (q >> 1);
                int n = n0 + nw * 16 + nt * 8 + 2 * lr + (q & 1);
                if (m < VV) {
                    float val = c[mt][nt][q] + bias[m];
                    int s0 = src[n], s1 = src[n + 64];
                    float sim = fminf(vs[(size_t)s0 * VV + m], vs[(size_t)s1 * VV + m]);
                    float md = fminf(sim, 20.0f);
                    float mult = (m == 3 || m == 4 || m == VV - 1) ? 1.0f
                                                                   : (md * md - 20.0f * md + 1.0f);
                    outp[(size_t)(n + 64) * VV + m] = val * mult;
                }
            }
        }
    }
}

/* ---------------- fence-free grid barrier ---------------- */
__device__ __forceinline__ void grid_barrier(unsigned nctas, unsigned& phase) {
    __syncthreads();
    phase++;
    if (threadIdx.x == 0) {
        asm volatile("red.release.gpu.global.add.u32 [%0], 1;"
                     :: "l"(&g_count) : "memory");
        unsigned need = phase * nctas;
        unsigned v;
        while (true) {
            asm volatile("ld.acquire.gpu.global.u32 %0, [%1];"
                         : "=r"(v) : "l"(&g_count) : "memory");
            if (v >= need) break;
            __nanosleep(32);
        }
    }
    __syncthreads();
}

/* ---------------- persistent LSTM recurrence (unchanged from R15) ---------------- */
__global__ void __launch_bounds__(RNN_THREADS, 1) rnn_kernel(const float* __restrict__ eb1,
                                                             const float* __restrict__ db1) {
    extern __shared__ float s_w[];
    const int tid  = threadIdx.x;
    const int lane = tid & 31;
    const int warp = tid >> 5;
    const int kp   = warp >> 2;
    const int ng   = warp & 3;
    const int tig  = lane & 3;
    const int gid  = lane >> 2;
    const int ncol0 = ng * 16 + gid;
    const int ublk = blockIdx.x * 4;
    const bool epi = (tid < 256);
    const int eu = (tid >> 6) & 3;
    const int eb = tid & 63;
    const unsigned nctas = gridDim.x;
    unsigned phase = 0;

    uint32 smem_base;
    asm("{ .reg .u64 t; cvta.to.shared.u64 t, %1; cvt.u32.u64 %0, t; }"
        : "=r"(smem_base) : "l"((void*)s_w));
    const uint32 stg_addr[2] = { smem_base + STG_F * 4u,
                                 smem_base + (STG_F + STG_BUF_F) * 4u };
    const uint32 mb_addr[2]  = { smem_base + MB_F * 4u, smem_base + MB_F * 4u + 8u };
    uint32 mb_ph[2] = { 0u, 0u };

    float c0s = 0.f, c1s = 0.f;
    float be[4], bd[4];
    #pragma unroll
    for (int g = 0; g < 4; g++) {
        be[g] = epi ? eb1[g * HH + ublk + eu] : 0.f;
        bd[g] = epi ? db1[g * HH + ublk + eu] : 0.f;
    }

    {
        const float4* src0 = (const float4*)&g_wf0e[blockIdx.x][0];
        const float4* src1 = (const float4*)&g_wf1e[blockIdx.x][0];
        float4* d0 = (float4*)&s_w[WF0_F];
        float4* d1 = (float4*)&s_w[WF1_F];
        for (int i = tid; i < 2048; i += RNN_THREADS) d0[i] = src0[i];
        for (int i = tid; i < 4096; i += RNN_THREADS) d1[i] = src1[i];
        for (int i = tid; i < 4352; i += RNN_THREADS) s_w[P0_F + i] = 0.f;
        if (tid == 0) { mbar_init(mb_addr[0], 1); mbar_init(mb_addr[1], 1); }
        __syncthreads();
    }

    for (int t = 0; t < NSTEP; t++) {
        const bool enc = (t < TT);

        if (epi) {
            float4 p = enc ? *(const float4*)&g_pre_e[t][ublk + eu][eb][0]
                           : *(const float4*)&g_pre_d[t - TT][ublk + eu][eb][0];
            float v[4];
            #pragma unroll
            for (int g = 0; g < 4; g++) {
                int m = eu * 4 + g;
                float s = 0.f;
                #pragma unroll
                for (int q = 0; q < 4; q++)
                    s += s_w[P0_F + q * 1088 + m * 68 + eb];
                v[g] = s;
            }
            float zi = v[0] + p.x, zf = v[1] + p.y, zg = v[2] + p.z, zo = v[3] + p.w;
            c0s = sigf(zf) * c0s + sigf(zi) * tanhf(zg);
            float hn = sigf(zo) * tanhf(c0s);
            g_h0[(t + 1) & 1][ublk + eu][eb] = __uint_as_float(tf32r(hn));
        }

        grid_barrier(nctas, phase);

        if (t == TT - 1) {
            const float4* src0 = (const float4*)&g_wf0d[blockIdx.x][0];
            float4* d0 = (float4*)&s_w[WF0_F];
            for (int i = tid; i < 2048; i += RNN_THREADS) d0[i] = src0[i];
            __syncthreads();
        }
        if (t == TT) {
            const float4* src1 = (const float4*)&g_wf1d[blockIdx.x][0];
            float4* d1 = (float4*)&s_w[WF1_F];
            for (int i = tid; i < 4096; i += RNN_THREADS) d1[i] = src1[i];
            __syncthreads();
        }

        {
            const float* h0new = &g_h0[(t + 1) & 1][0][0];
            const float* h1old = &g_h1[t & 1][0][0];
            float a1[2][4], a0[2][4];
            #pragma unroll
            for (int nt = 0; nt < 2; nt++)
                #pragma unroll
                for (int q = 0; q < 4; q++) { a1[nt][q] = 0.f; a0[nt][q] = 0.f; }

            if (tid == 0) {
                mbar_expect_tx(mb_addr[0], CHUNK_BYTES);
                bulk_copy(stg_addr[0], h0new, CHUNK_BYTES, mb_addr[0]);
            }
            #pragma unroll
            for (int ch = 0; ch < 8; ch++) {
                if (ch + 1 < 8 && tid == 0) {
                    const float* nxt = (ch + 1 < 4) ? (h0new + (ch + 1) * 128 * HS)
                                                    : (h1old + (ch - 3) * 128 * HS);
                    int nb = (ch + 1) & 1;
                    mbar_expect_tx(mb_addr[nb], CHUNK_BYTES);
                    bulk_copy(stg_addr[nb], nxt, CHUNK_BYTES, mb_addr[nb]);
                }
                int cb = ch & 1;
                mbar_wait(mb_addr[cb], mb_ph[cb] & 1u);
                mb_ph[cb]++;

                const float* stg = &s_w[STG_F + cb * STG_BUF_F];
                #pragma unroll
                for (int cc = 0; cc < 4; cc++) {
                    int kcg = ch * 16 + kp * 4 + cc;
                    int krl = (kp * 4 + cc) * 8 + tig;
                    float b0[2], b1[2];
                    #pragma unroll
                    for (int nt = 0; nt < 2; nt++) {
                        b0[nt] = stg[krl * 72 + ncol0 + nt * 8];
                        b1[nt] = stg[(krl + 4) * 72 + ncol0 + nt * 8];
                    }
                    float4 af1 = *(const float4*)&s_w[WF1_F + (kcg * 32 + lane) * 4];
                    #pragma unroll
                    for (int nt = 0; nt < 2; nt++)
                        mma_tf32(a1[nt], __float_as_uint(af1.x), __float_as_uint(af1.y),
                                 __float_as_uint(af1.z), __float_as_uint(af1.w),
                                 __float_as_uint(b0[nt]), __float_as_uint(b1[nt]));
                    if (ch < 4) {
                        float4 af0 = *(const float4*)&s_w[WF0_F + (kcg * 32 + lane) * 4];
                        #pragma unroll
                        for (int nt = 0; nt < 2; nt++)
                            mma_tf32(a0[nt], __float_as_uint(af0.x), __float_as_uint(af0.y),
                                     __float_as_uint(af0.z), __float_as_uint(af0.w),
                                     __float_as_uint(b0[nt]), __float_as_uint(b1[nt]));
                    }
                }
                __syncthreads();
            }
            #pragma unroll
            for (int nt = 0; nt < 2; nt++) {
                int colb = ng * 16 + nt * 8 + 2 * tig;
                *(float2*)&s_w[P1_F + kp * 1088 + gid * 68 + colb] =
                    make_float2(a1[nt][0], a1[nt][1]);
                *(float2*)&s_w[P1_F + kp * 1088 + (gid + 8) * 68 + colb] =
                    make_float2(a1[nt][2], a1[nt][3]);
                *(float2*)&s_w[P0_F + kp * 1088 + gid * 68 + colb] =
                    make_float2(a0[nt][0], a0[nt][1]);
                *(float2*)&s_w[P0_F + kp * 1088 + (gid + 8) * 68 + colb] =
                    make_float2(a0[nt][2], a0[nt][3]);
            }
        }
        __syncthreads();

        if (epi) {
            float v[4];
            #pragma unroll
            for (int g = 0; g < 4; g++) {
                int m = eu * 4 + g;
                float s = 0.f;
                #pragma unroll
                for (int q = 0; q < 4; q++)
                    s += s_w[P1_F + q * 1088 + m * 68 + eb];
                v[g] = s;
            }
            float bi = enc ? be[0] : bd[0];
            float bf = enc ? be[1] : bd[1];
            float bg = enc ? be[2] : bd[2];
            float bo = enc ? be[3] : bd[3];
            float zi = v[0] + bi, zf = v[1] + bf, zg = v[2] + bg, zo = v[3] + bo;
            c1s = sigf(zf) * c1s + sigf(zi) * tanhf(zg);
            float hn = sigf(zo) * tanhf(c1s);
            g_h1[(t + 1) & 1][ublk + eu][eb] = __uint_as_float(tf32r(hn));
            if (!enc) g_hist[(t - TT) * BB + eb][ublk + eu] = hn;
        }
    }
}

/* ---------------- launch ---------------- */
extern "C" void kernel_launch(void* const* d_in, const int* in_sizes, int n_in,
                              void* d_out, int out_size) {
    const void* in[32];
    int j = 0;
    for (int k = 0; k < n_in && j < 32; k++) {
        if (in_sizes[k] == 1) continue;       /* skip scalar src_lens/trg_lens */
        in[j++] = d_in[k];
    }
    const int*   src   = (const int*)in[0];
    const int*   trg   = (const int*)in[1];
    const float* vs    = (const float*)in[2];
    const float* embE  = (const float*)in[3];
    const float* embD  = (const float*)in[4];
    const float* eWih0 = (const float*)in[5];
    const float* eWhh0 = (const float*)in[6];
    const float* eb0   = (const float*)in[7];
    const float* eWih1 = (const float*)in[8];
    const float* eWhh1 = (const float*)in[9];
    const float* eb1   = (const float*)in[10];
    const float* dWih0 = (const float*)in[11];
    const float* dWhh0 = (const float*)in[12];
    const float* db0   = (const float*)in[13];
    const float* dWih1 = (const float*)in[14];
    const float* dWhh1 = (const float*)in[15];
    const float* db1   = (const float*)in[16];
    const float* fcW   = (const float*)in[17];
    const float* fcb   = (const float*)in[18];
    float* out = (float*)d_out;

    static int smem_set = 0;
    if (!smem_set) {
        cudaFuncSetAttribute(rnn_kernel, cudaFuncAttributeMaxDynamicSharedMemorySize,
                             RNN_SMEM_BYTES);
        smem_set = 1;
    }

    /* 1: setup (out zero + h init + flags + both gathers) */
    setup_kernel<<<4080, 256>>>(out, embE, src, embD, trg);
    /* 2: weight repack into mma fragment order (tf32) */
    repack_kernel<<<512, 256>>>(eWhh0, dWhh0, eWih1, eWhh1, dWih1, dWhh1);
    /* 3: merged layer-0 input preactivations (fp32) */
    gemm_kernel<<<dim3(NCOLS_E / 64 + NCOLS_D / 64, 2048 / 64), 256>>>(
        eWih0, dWih0, 2048, EE, eb0, db0);
    /* 4: serial recurrence (fused-stream tensor mma + bulk staging) */
    rnn_kernel<<<RNN_CTAS, RNN_THREADS, RNN_SMEM_BYTES>>>(eb1, db1);
    /* 5: vocab projection + similarity mask (tf32 mma) */
    fc_tc_kernel<<<dim3(NCOLS_D / 64, (VV + 63) / 64), 256>>>(fcW, fcb, src, vs, out);
}

// round 17
// speedup vs baseline: 1.1817x; 1.1817x over previous
#include <cuda_runtime.h>
#include <cuda_bf16.h>
#include <cstdint>

typedef unsigned long long ull;
typedef unsigned int uint32;

#define TT   128
#define BB   64
#define HS   72          /* padded global h row stride (floats) */
#define HH   512
#define EE   256
#define VV   5000
#define NSTEP 255
#define NCOLS_E 8192
#define NCOLS_D 8128
#define RNN_CTAS 128
#define RNN_THREADS 512
/* rnn smem (floats): wf0 8192 | wf1 16384 | stage 2x(128x72)=18432 | P0 4352 | P1 4352 | mbar 4 */
#define WF0_F  0
#define WF1_F  8192
#define STG_F  24576
#define STG_BUF_F 9216
#define P0_F   43008
#define P1_F   47360
#define MB_F   51712
#define RNN_SMEM_FLOATS 51716
#define RNN_SMEM_BYTES  (RNN_SMEM_FLOATS * 4)
#define CHUNK_BYTES (128 * HS * 4)   /* 36864 */

/* ---------------- device scratch (static, no allocation) ---------------- */
__device__ float g_xe[NCOLS_E][EE];
__device__ float g_xd[NCOLS_D][EE];
__device__ float g_pre_e[TT][HH][BB][4];
__device__ float g_pre_d[TT - 1][HH][BB][4];
__device__ float g_wf0e[RNN_CTAS][8192];
__device__ float g_wf0d[RNN_CTAS][8192];
__device__ float g_wf1e[RNN_CTAS][16384];
__device__ float g_wf1d[RNN_CTAS][16384];
__device__ float g_h0[2][HH][HS];
__device__ float g_h1[2][HH][HS];
__device__ float g_hist[NCOLS_D][HH];
__device__ unsigned g_count;

/* ---------------- helpers ---------------- */
__device__ __forceinline__ void fma2(ull& acc, ull a, ull b) {
    asm("fma.rn.f32x2 %0, %1, %2, %0;" : "+l"(acc) : "l"(a), "l"(b));
}
__device__ __forceinline__ ull splat2(float x) {
    ull r; unsigned u = __float_as_uint(x);
    asm("mov.b64 %0, {%1, %1};" : "=l"(r) : "r"(u));
    return r;
}
__device__ __forceinline__ float2 unpack2(ull v) {
    unsigned lo, hi;
    asm("mov.b64 {%0, %1}, %2;" : "=r"(lo), "=r"(hi) : "l"(v));
    float2 f; f.x = __uint_as_float(lo); f.y = __uint_as_float(hi);
    return f;
}
__device__ __forceinline__ float sigf(float x) { return 1.0f / (1.0f + __expf(-x)); }
__device__ __forceinline__ uint32 tf32r(float x) {
    uint32 r; asm("cvt.rna.tf32.f32 %0, %1;" : "=r"(r) : "f"(x));
    return r;
}
__device__ __forceinline__ void mma_tf32(float* c,
                                         uint32 a0, uint32 a1, uint32 a2, uint32 a3,
                                         uint32 b0, uint32 b1) {
    asm volatile(
        "mma.sync.aligned.m16n8k8.row.col.f32.tf32.tf32.f32 "
        "{%0,%1,%2,%3}, {%4,%5,%6,%7}, {%8,%9}, {%0,%1,%2,%3};"
        : "+f"(c[0]), "+f"(c[1]), "+f"(c[2]), "+f"(c[3])
        : "r"(a0), "r"(a1), "r"(a2), "r"(a3), "r"(b0), "r"(b1));
}
__device__ __forceinline__ void mbar_init(uint32 mbar, uint32 cnt) {
    asm volatile("mbarrier.init.shared.b64 [%0], %1;" :: "r"(mbar), "r"(cnt) : "memory");
}
__device__ __forceinline__ void mbar_expect_tx(uint32 mbar, uint32 bytes) {
    asm volatile("mbarrier.arrive.expect_tx.shared.b64 _, [%0], %1;"
                 :: "r"(mbar), "r"(bytes) : "memory");
}
__device__ __forceinline__ void bulk_copy(uint32 sdst, const void* gsrc, uint32 bytes,
                                          uint32 mbar) {
    asm volatile("cp.async.bulk.shared::cta.global.mbarrier::complete_tx::bytes "
                 "[%0], [%1], %2, [%3];"
                 :: "r"(sdst), "l"(gsrc), "r"(bytes), "r"(mbar) : "memory");
}
__device__ __forceinline__ void mbar_wait(uint32 mbar, uint32 parity) {
    uint32 done;
    asm volatile("{\n\t.reg .pred p;\n\t"
                 "mbarrier.try_wait.parity.acquire.cta.shared::cta.b64 p, [%1], %2;\n\t"
                 "selp.b32 %0, 1, 0, p;\n\t}"
                 : "=r"(done) : "r"(mbar), "r"(parity) : "memory");
    if (!done) {
        asm volatile("{\n\t.reg .pred P1;\n\t"
                     "WL_%=:\n\t"
                     "mbarrier.try_wait.parity.acquire.cta.shared::cta.b64 P1, [%0], %1, 0x989680;\n\t"
                     "@P1 bra.uni WD_%=;\n\t"
                     "bra.uni WL_%=;\n\t"
                     "WD_%=:\n\t}"
                     :: "r"(mbar), "r"(parity) : "memory");
    }
}

/* ---------------- setup ---------------- */
__global__ void setup_kernel(float* __restrict__ out,
                             const float* __restrict__ embE, const int* __restrict__ src,
                             const float* __restrict__ embD, const int* __restrict__ trg) {
    int i = blockIdx.x * blockDim.x + threadIdx.x;
    if (i < NCOLS_E * 64) {
        int col = i >> 6, e4 = i & 63;
        ((float4*)&g_xe[0][0])[(size_t)col * 64 + e4] =
            ((const float4*)embE)[(size_t)src[col] * 64 + e4];
    } else if (i < NCOLS_E * 64 + NCOLS_D * 64) {
        int j2 = i - NCOLS_E * 64;
        int col = j2 >> 6, e4 = j2 & 63;
        ((float4*)&g_xd[0][0])[(size_t)col * 64 + e4] =
            ((const float4*)embD)[(size_t)trg[col] * 64 + e4];
    }
    if (i < BB * VV) out[i] = 0.0f;
    if (i < 2 * HH * HS) {
        (&g_h0[0][0][0])[i] = 0.0f;
        (&g_h1[0][0][0])[i] = 0.0f;
    }
    if (i == 0) g_count = 0u;
}

/* ---------------- weight repack into mma fragment order (tf32-rounded) ---------------- */
__global__ void repack_kernel(const float* __restrict__ eWhh0, const float* __restrict__ dWhh0,
                              const float* __restrict__ eWih1, const float* __restrict__ eWhh1,
                              const float* __restrict__ dWih1, const float* __restrict__ dWhh1) {
    int stride = gridDim.x * blockDim.x;
    int idx = blockIdx.x * blockDim.x + threadIdx.x;
    for (int i = idx; i < RNN_CTAS * 8192; i += stride) {
        int j = i & 3, l = (i >> 2) & 31, c = (i >> 7) & 63, cta = i >> 13;
        int m = (l >> 2) + ((j & 1) << 3);
        int k = 8 * c + (l & 3) + ((j >> 1) << 2);
        int u = cta * 4 + (m >> 2), g = m & 3;
        size_t off = (size_t)(g * HH + u) * HH + k;
        g_wf0e[cta][i & 8191] = __uint_as_float(tf32r(eWhh0[off]));
        g_wf0d[cta][i & 8191] = __uint_as_float(tf32r(dWhh0[off]));
    }
    for (int i = idx; i < RNN_CTAS * 16384; i += stride) {
        int j = i & 3, l = (i >> 2) & 31, c = (i >> 7) & 127, cta = i >> 14;
        int m = (l >> 2) + ((j & 1) << 3);
        int k = 8 * c + (l & 3) + ((j >> 1) << 2);
        int u = cta * 4 + (m >> 2), g = m & 3;
        float ve, vd;
        if (k < HH) { ve = eWih1[(size_t)(g * HH + u) * HH + k];
                      vd = dWih1[(size_t)(g * HH + u) * HH + k]; }
        else        { ve = eWhh1[(size_t)(g * HH + u) * HH + (k - HH)];
                      vd = dWhh1[(size_t)(g * HH + u) * HH + (k - HH)]; }
        g_wf1e[cta][i & 16383] = __uint_as_float(tf32r(ve));
        g_wf1d[cta][i & 16383] = __uint_as_float(tf32r(vd));
    }
}

/* ---------------- generic 64x64 tiled fp32 GEMM, C = A(MxK) * B(NxK)^T ----------------
   mode 0: layer-0 preactivations (enc/dec split by blockIdx.x)
   mode 2: fc + similarity mask epilogue                                        */
__global__ void __launch_bounds__(256) gemm_kernel(
    const float* __restrict__ Aenc, const float* __restrict__ Adec,
    int M, int K, int mode,
    const float* __restrict__ biasE, const float* __restrict__ biasD,
    const int* __restrict__ src, const float* __restrict__ vs,
    float* __restrict__ outp) {
    __shared__ float As[32][64];
    __shared__ float Bs[32][64];

    int tid = threadIdx.x;
    int r = (tid & 15) << 2;
    int c = (tid >> 4) << 2;
    int m0 = blockIdx.y * 64;

    const float* A;
    const float* bias;
    const float* B;
    float* dst = nullptr;
    int n0;
    if (mode == 0) {
        bool dec = (blockIdx.x >= NCOLS_E / 64);
        A    = dec ? Adec : Aenc;
        bias = dec ? biasD : biasE;
        B    = dec ? &g_xd[0][0] : &g_xe[0][0];
        dst  = dec ? &g_pre_d[0][0][0][0] : &g_pre_e[0][0][0][0];
        n0   = (dec ? (int)blockIdx.x - NCOLS_E / 64 : (int)blockIdx.x) * 64;
    } else {
        A = Aenc; bias = biasE; B = &g_hist[0][0];
        n0 = blockIdx.x * 64;
    }

    ull acc[4][2];
    #pragma unroll
    for (int i = 0; i < 4; i++) { acc[i][0] = 0ull; acc[i][1] = 0ull; }

    for (int kt = 0; kt < K; kt += 32) {
        #pragma unroll
        for (int rep = 0; rep < 2; rep++) {
            int f = tid + rep * 256;
            int m = f >> 3;
            int k4 = (f & 7) << 2;
            int gm = m0 + m;
            float4 va = make_float4(0.f, 0.f, 0.f, 0.f);
            if (gm < M) va = *(const float4*)&A[(size_t)gm * K + kt + k4];
            As[k4 + 0][m] = va.x; As[k4 + 1][m] = va.y;
            As[k4 + 2][m] = va.z; As[k4 + 3][m] = va.w;
            float4 vb = *(const float4*)&B[(size_t)(n0 + m) * K + kt + k4];
            Bs[k4 + 0][m] = vb.x; Bs[k4 + 1][m] = vb.y;
            Bs[k4 + 2][m] = vb.z; Bs[k4 + 3][m] = vb.w;
        }
        __syncthreads();
        #pragma unroll
        for (int k = 0; k < 32; k++) {
            float4 av = *(const float4*)&As[k][r];
            float4 bv = *(const float4*)&Bs[k][c];
            ull b01 = ((const ull*)&bv)[0];
            ull b23 = ((const ull*)&bv)[1];
            ull a0 = splat2(av.x), a1 = splat2(av.y), a2 = splat2(av.z), a3 = splat2(av.w);
            fma2(acc[0][0], a0, b01); fma2(acc[0][1], a0, b23);
            fma2(acc[1][0], a1, b01); fma2(acc[1][1], a1, b23);
            fma2(acc[2][0], a2, b01); fma2(acc[2][1], a2, b23);
            fma2(acc[3][0], a3, b01); fma2(acc[3][1], a3, b23);
        }
        __syncthreads();
    }

    #pragma unroll
    for (int i = 0; i < 4; i++) {
        int m = m0 + r + i;
        if (m >= M) continue;
        float bval = bias[m];
        float2 v01 = unpack2(acc[i][0]);
        float2 v23 = unpack2(acc[i][1]);
        float vals[4] = { v01.x + bval, v01.y + bval, v23.x + bval, v23.y + bval };
        #pragma unroll
        for (int j = 0; j < 4; j++) {
            int n = n0 + c + j;
            if (mode == 2) {
                int s0 = src[n], s1 = src[n + 64];
                float sim = fminf(vs[(size_t)s0 * VV + m], vs[(size_t)s1 * VV + m]);
                float md = fminf(sim, 20.0f);
                float mult = (m == 3 || m == 4 || m == VV - 1) ? 1.0f
                                                               : (md * md - 20.0f * md + 1.0f);
                outp[(size_t)(n + 64) * VV + m] = vals[j] * mult;
            } else {
                int t = n >> 6, b = n & 63;
                int uu = m & 511, g = m >> 9;
                dst[(((size_t)t * HH + uu) * BB + b) * 4 + g] = vals[j];
            }
        }
    }
}

/* ---------------- fence-free grid barrier ---------------- */
__device__ __forceinline__ void grid_barrier(unsigned nctas, unsigned& phase) {
    __syncthreads();
    phase++;
    if (threadIdx.x == 0) {
        asm volatile("red.release.gpu.global.add.u32 [%0], 1;"
                     :: "l"(&g_count) : "memory");
        unsigned need = phase * nctas;
        unsigned v;
        while (true) {
            asm volatile("ld.acquire.gpu.global.u32 %0, [%1];"
                         : "=r"(v) : "l"(&g_count) : "memory");
            if (v >= need) break;
            __nanosleep(32);
        }
    }
    __syncthreads();
}

/* ---------------- persistent LSTM recurrence: FUSED stream + DUAL epilogue ----------------
   Step t body:  barrier -> [weight swaps] -> fused(t) -> sync ->
                 threads   0-255: L1-epilogue(t)   (P1(t), c1, -> g_h1[(t+1)&1], hist)
                 threads 256-511: L0-epilogue(t+1) (P0(t+1), pre[t+1], c0, -> g_h0[(t+2)&1])
   The two epilogues are independent (disjoint state/buffers) and run in parallel.
   Initial L0-epilogue(0) (zero P0 + pre[0]) runs on the high half before the loop.
   Hazard: writing g_h0[(t+2)&1]=g_h0[t&1] pre-barrier is safe: its last cross-CTA
   reads (fused(t-1) h0new staging) complete before any CTA passes barrier(t).        */
__global__ void __launch_bounds__(RNN_THREADS, 1) rnn_kernel(const float* __restrict__ eb1,
                                                             const float* __restrict__ db1) {
    extern __shared__ float s_w[];
    const int tid  = threadIdx.x;
    const int lane = tid & 31;
    const int warp = tid >> 5;
    const int kp   = warp >> 2;
    const int ng   = warp & 3;
    const int tig  = lane & 3;
    const int gid  = lane >> 2;
    const int ncol0 = ng * 16 + gid;
    const int ublk = blockIdx.x * 4;
    const bool lo = (tid < 256);           /* low half: L1-epi ; high half: L0-epi */
    const int eu = (tid >> 6) & 3;
    const int eb = tid & 63;
    const unsigned nctas = gridDim.x;
    unsigned phase = 0;

    uint32 smem_base;
    asm("{ .reg .u64 t; cvta.to.shared.u64 t, %1; cvt.u32.u64 %0, t; }"
        : "=r"(smem_base) : "l"((void*)s_w));
    const uint32 stg_addr[2] = { smem_base + STG_F * 4u,
                                 smem_base + (STG_F + STG_BUF_F) * 4u };
    const uint32 mb_addr[2]  = { smem_base + MB_F * 4u, smem_base + MB_F * 4u + 8u };
    uint32 mb_ph[2] = { 0u, 0u };

    float c0s = 0.f;   /* live in high half */
    float c1s = 0.f;   /* live in low half  */
    float be[4], bd[4];
    #pragma unroll
    for (int g = 0; g < 4; g++) {
        be[g] = lo ? eb1[g * HH + ublk + eu] : 0.f;
        bd[g] = lo ? db1[g * HH + ublk + eu] : 0.f;
    }

    /* init: enc weights + zero P0 + mbarriers */
    {
        const float4* src0 = (const float4*)&g_wf0e[blockIdx.x][0];
        const float4* src1 = (const float4*)&g_wf1e[blockIdx.x][0];
        float4* d0 = (float4*)&s_w[WF0_F];
        float4* d1 = (float4*)&s_w[WF1_F];
        for (int i = tid; i < 2048; i += RNN_THREADS) d0[i] = src0[i];
        for (int i = tid; i < 4096; i += RNN_THREADS) d1[i] = src1[i];
        for (int i = tid; i < 4352; i += RNN_THREADS) s_w[P0_F + i] = 0.f;
        if (tid == 0) { mbar_init(mb_addr[0], 1); mbar_init(mb_addr[1], 1); }
        __syncthreads();
    }

    /* initial L0-epilogue(0): P0 = 0, add pre[0] (high half) */
    if (!lo) {
        float4 p = *(const float4*)&g_pre_e[0][ublk + eu][eb][0];
        float v[4];
        #pragma unroll
        for (int g = 0; g < 4; g++) {
            int m = eu * 4 + g;
            float s = 0.f;
            #pragma unroll
            for (int q = 0; q < 4; q++) s += s_w[P0_F + q * 1088 + m * 68 + eb];
            v[g] = s;
        }
        float zi = v[0] + p.x, zf = v[1] + p.y, zg = v[2] + p.z, zo = v[3] + p.w;
        c0s = sigf(zf) * c0s + sigf(zi) * tanhf(zg);
        float hn = sigf(zo) * tanhf(c0s);
        g_h0[1][ublk + eu][eb] = __uint_as_float(tf32r(hn));
    }

    for (int t = 0; t < NSTEP; t++) {
        const bool enc = (t < TT);

        grid_barrier(nctas, phase);

        /* weight swaps */
        if (t == TT - 1) {
            const float4* src0 = (const float4*)&g_wf0d[blockIdx.x][0];
            float4* d0 = (float4*)&s_w[WF0_F];
            for (int i = tid; i < 2048; i += RNN_THREADS) d0[i] = src0[i];
            __syncthreads();
        }
        if (t == TT) {
            const float4* src1 = (const float4*)&g_wf1d[blockIdx.x][0];
            float4* d1 = (float4*)&s_w[WF1_F];
            for (int i = tid; i < 4096; i += RNN_THREADS) d1[i] = src1[i];
            __syncthreads();
        }

        /* ================= fused phase: 8 bulk-staged chunks ================= */
        {
            const float* h0new = &g_h0[(t + 1) & 1][0][0];
            const float* h1old = &g_h1[t & 1][0][0];
            float a1[2][4], a0[2][4];
            #pragma unroll
            for (int nt = 0; nt < 2; nt++)
                #pragma unroll
                for (int q = 0; q < 4; q++) { a1[nt][q] = 0.f; a0[nt][q] = 0.f; }

            if (tid == 0) {
                mbar_expect_tx(mb_addr[0], CHUNK_BYTES);
                bulk_copy(stg_addr[0], h0new, CHUNK_BYTES, mb_addr[0]);
            }
            #pragma unroll
            for (int ch = 0; ch < 8; ch++) {
                if (ch + 1 < 8 && tid == 0) {
                    const float* nxt = (ch + 1 < 4) ? (h0new + (ch + 1) * 128 * HS)
                                                    : (h1old + (ch - 3) * 128 * HS);
                    int nb = (ch + 1) & 1;
                    mbar_expect_tx(mb_addr[nb], CHUNK_BYTES);
                    bulk_copy(stg_addr[nb], nxt, CHUNK_BYTES, mb_addr[nb]);
                }
                int cb = ch & 1;
                mbar_wait(mb_addr[cb], mb_ph[cb] & 1u);
                mb_ph[cb]++;

                const float* stg = &s_w[STG_F + cb * STG_BUF_F];
                #pragma unroll
                for (int cc = 0; cc < 4; cc++) {
                    int kcg = ch * 16 + kp * 4 + cc;
                    int krl = (kp * 4 + cc) * 8 + tig;
                    float b0[2], b1[2];
                    #pragma unroll
                    for (int nt = 0; nt < 2; nt++) {
                        b0[nt] = stg[krl * 72 + ncol0 + nt * 8];
                        b1[nt] = stg[(krl + 4) * 72 + ncol0 + nt * 8];
                    }
                    float4 af1 = *(const float4*)&s_w[WF1_F + (kcg * 32 + lane) * 4];
                    #pragma unroll
                    for (int nt = 0; nt < 2; nt++)
                        mma_tf32(a1[nt], __float_as_uint(af1.x), __float_as_uint(af1.y),
                                 __float_as_uint(af1.z), __float_as_uint(af1.w),
                                 __float_as_uint(b0[nt]), __float_as_uint(b1[nt]));
                    if (ch < 4) {
                        float4 af0 = *(const float4*)&s_w[WF0_F + (kcg * 32 + lane) * 4];
                        #pragma unroll
                        for (int nt = 0; nt < 2; nt++)
                            mma_tf32(a0[nt], __float_as_uint(af0.x), __float_as_uint(af0.y),
                                     __float_as_uint(af0.z), __float_as_uint(af0.w),
                                     __float_as_uint(b0[nt]), __float_as_uint(b1[nt]));
                    }
                }
                if (ch + 1 < 8) __syncthreads();   /* protect buffer refill (skip last) */
            }
            /* store partials: P1(t) and P0(t+1) */
            #pragma unroll
            for (int nt = 0; nt < 2; nt++) {
                int colb = ng * 16 + nt * 8 + 2 * tig;
                *(float2*)&s_w[P1_F + kp * 1088 + gid * 68 + colb] =
                    make_float2(a1[nt][0], a1[nt][1]);
                *(float2*)&s_w[P1_F + kp * 1088 + (gid + 8) * 68 + colb] =
                    make_float2(a1[nt][2], a1[nt][3]);
                *(float2*)&s_w[P0_F + kp * 1088 + gid * 68 + colb] =
                    make_float2(a0[nt][0], a0[nt][1]);
                *(float2*)&s_w[P0_F + kp * 1088 + (gid + 8) * 68 + colb] =
                    make_float2(a0[nt][2], a0[nt][3]);
            }
        }
        __syncthreads();

        /* ---- DUAL epilogue ---- */
        if (lo) {
            /* L1-epilogue(t) */
            float v[4];
            #pragma unroll
            for (int g = 0; g < 4; g++) {
                int m = eu * 4 + g;
                float s = 0.f;
                #pragma unroll
                for (int q = 0; q < 4; q++) s += s_w[P1_F + q * 1088 + m * 68 + eb];
                v[g] = s;
            }
            float bi = enc ? be[0] : bd[0];
            float bf = enc ? be[1] : bd[1];
            float bg = enc ? be[2] : bd[2];
            float bo = enc ? be[3] : bd[3];
            float zi = v[0] + bi, zf = v[1] + bf, zg = v[2] + bg, zo = v[3] + bo;
            c1s = sigf(zf) * c1s + sigf(zi) * tanhf(zg);
            float hn = sigf(zo) * tanhf(c1s);
            g_h1[(t + 1) & 1][ublk + eu][eb] = __uint_as_float(tf32r(hn));
            if (!enc) g_hist[(t - TT) * BB + eb][ublk + eu] = hn;
        } else if (t + 1 < NSTEP) {
            /* L0-epilogue(t+1) */
            const bool enc1 = (t + 1 < TT);
            float4 p = enc1 ? *(const float4*)&g_pre_e[t + 1][ublk + eu][eb][0]
                            : *(const float4*)&g_pre_d[t + 1 - TT][ublk + eu][eb][0];
            float v[4];
            #pragma unroll
            for (int g = 0; g < 4; g++) {
                int m = eu * 4 + g;
                float s = 0.f;
                #pragma unroll
                for (int q = 0; q < 4; q++) s += s_w[P0_F + q * 1088 + m * 68 + eb];
                v[g] = s;
            }
            float zi = v[0] + p.x, zf = v[1] + p.y, zg = v[2] + p.z, zo = v[3] + p.w;
            c0s = sigf(zf) * c0s + sigf(zi) * tanhf(zg);
            float hn = sigf(zo) * tanhf(c0s);
            g_h0[(t + 2) & 1][ublk + eu][eb] = __uint_as_float(tf32r(hn));
        }
        /* hazards: write g_h0[(t+2)&1] is WAR-safe (see header note); g_h1[(t+1)&1]
           is read only in fused(t+1) after barrier(t+1); P buffers are rewritten
           only in fused(t+1), after barrier(t+1)'s entry sync.                   */
    }
}

/* ---------------- launch ---------------- */
extern "C" void kernel_launch(void* const* d_in, const int* in_sizes, int n_in,
                              void* d_out, int out_size) {
    const void* in[32];
    int j = 0;
    for (int k = 0; k < n_in && j < 32; k++) {
        if (in_sizes[k] == 1) continue;       /* skip scalar src_lens/trg_lens */
        in[j++] = d_in[k];
    }
    const int*   src   = (const int*)in[0];
    const int*   trg   = (const int*)in[1];
    const float* vs    = (const float*)in[2];
    const float* embE  = (const float*)in[3];
    const float* embD  = (const float*)in[4];
    const float* eWih0 = (const float*)in[5];
    const float* eWhh0 = (const float*)in[6];
    const float* eb0   = (const float*)in[7];
    const float* eWih1 = (const float*)in[8];
    const float* eWhh1 = (const float*)in[9];
    const float* eb1   = (const float*)in[10];
    const float* dWih0 = (const float*)in[11];
    const float* dWhh0 = (const float*)in[12];
    const float* db0   = (const float*)in[13];
    const float* dWih1 = (const float*)in[14];
    const float* dWhh1 = (const float*)in[15];
    const float* db1   = (const float*)in[16];
    const float* fcW   = (const float*)in[17];
    const float* fcb   = (const float*)in[18];
    float* out = (float*)d_out;

    static int smem_set = 0;
    if (!smem_set) {
        cudaFuncSetAttribute(rnn_kernel, cudaFuncAttributeMaxDynamicSharedMemorySize,
                             RNN_SMEM_BYTES);
        smem_set = 1;
    }

    /* 1: setup (out zero + h init + flags + both gathers) */
    setup_kernel<<<4080, 256>>>(out, embE, src, embD, trg);
    /* 2: weight repack into mma fragment order (tf32) */
    repack_kernel<<<512, 256>>>(eWhh0, dWhh0, eWih1, eWhh1, dWih1, dWhh1);
    /* 3: merged layer-0 input preactivations (fp32) */
    gemm_kernel<<<dim3(NCOLS_E / 64 + NCOLS_D / 64, 2048 / 64), 256>>>(
        eWih0, dWih0, 2048, EE, 0, eb0, db0, nullptr, nullptr, nullptr);
    /* 4: serial recurrence (fused-stream tensor mma + bulk staging + dual epilogue) */
    rnn_kernel<<<RNN_CTAS, RNN_THREADS, RNN_SMEM_BYTES>>>(eb1, db1);
    /* 5: vocab projection + similarity mask (fp32 — R15 proven path) */
    gemm_kernel<<<dim3(NCOLS_D / 64, (VV + 63) / 64), 256>>>(
        fcW, nullptr, VV, HH, 2, fcb, nullptr, src, vs, out);
}